// round 3
// baseline (speedup 1.0000x reference)
#include <cuda_runtime.h>
#include <math.h>

#define BB 16
#define TT 32

__constant__ float c_anch[18] = {
    10.f/8.f, 13.f/8.f, 16.f/8.f, 30.f/8.f, 33.f/8.f, 23.f/8.f,
    30.f/16.f, 61.f/16.f, 62.f/16.f, 45.f/16.f, 59.f/16.f, 119.f/16.f,
    116.f/32.f, 90.f/32.f, 156.f/32.f, 198.f/32.f, 373.f/32.f, 326.f/32.f
};

// Dense geometry: runs of 5 contiguous channels per (b,anchor): run = b*3+a.
// scale0: 48 runs x 8000 f4 (HW4=1600), 4 chunks of 2048 -> 192 blocks
// scale1: 48 runs x 2000 f4 (HW4=400),  1 chunk          ->  48 blocks
// scale2: 48 runs x  500 f4 (HW4=100),  1 chunk          ->  48 blocks
#define DB0 192
#define DB1 48
#define DB2 48
#define NDB (DB0 + DB1 + DB2)    // 288 dense blocks
#define NCB 48                   // corr blocks (16 per scale)
#define NBLK (NDB + NCB)         // 336 total, all 512 threads

__device__ float g_bpart[NDB][2];   // per dense block: sum p^2, sum softplus
__device__ float g_cpart[NCB][5];   // per corr block: bd, os, ns, cs, n_valid
__device__ int   g_ticket;          // zero-init; last block resets to 0

__device__ __forceinline__ float sp(float x) {
    return fmaxf(x, 0.f) + log1pf(expf(-fabsf(x)));
}

__device__ __forceinline__ float warp_sum(float v) {
    #pragma unroll
    for (int o = 16; o; o >>= 1) v += __shfl_down_sync(0xffffffffu, v, o);
    return v;
}

__global__ void __launch_bounds__(512)
fused_kernel(const float* __restrict__ p0,
             const float* __restrict__ p1,
             const float* __restrict__ p2,
             const float* __restrict__ targets,
             float* __restrict__ out) {
    const int bid = blockIdx.x, tid = threadIdx.x;
    const int lane = tid & 31, w = tid >> 5;

    __shared__ int   s_lin[512];
    __shared__ int   s_val[512];
    __shared__ int   s_ok[512];
    __shared__ int   s_meta[512];
    __shared__ float s_tb[512][4];
    __shared__ float red[16][5];

    if (bid < NDB) {
        // ---------------- dense base pass ----------------
        const float* p; int basef4, f0, nf4, boxlim;
        if (bid < DB0) {
            const int run = bid >> 2, chunk = bid & 3;
            p = p0; basef4 = run * 40000; f0 = chunk * 2048;
            nf4 = 8000; boxlim = 6400;
        } else if (bid < DB0 + DB1) {
            const int run = bid - DB0;
            p = p1; basef4 = run * 10000; f0 = 0;
            nf4 = 2000; boxlim = 1600;
        } else {
            const int run = bid - DB0 - DB1;
            p = p2; basef4 = run * 2500; f0 = 0;
            nf4 = 500; boxlim = 400;
        }
        const float4* p4 = reinterpret_cast<const float4*>(p) + basef4;

        // front-batched loads: 4 independent LDG.128 per thread
        float4 v[4];
        bool isbox[4];
        #pragma unroll
        for (int k = 0; k < 4; k++) {
            const int f = f0 + k * 512 + tid;
            const bool ok = f < nf4;
            v[k] = ok ? p4[f] : make_float4(0.f, 0.f, 0.f, 0.f);
            isbox[k] = (!ok) || (f < boxlim);   // zeros go through box path (add 0)
        }

        float bacc = 0.f, sacc = 0.f;
        #pragma unroll
        for (int k = 0; k < 4; k++) {
            if (isbox[k]) {
                bacc += v[k].x * v[k].x + v[k].y * v[k].y
                      + v[k].z * v[k].z + v[k].w * v[k].w;
            } else {
                sacc += sp(v[k].x) + sp(v[k].y) + sp(v[k].z) + sp(v[k].w);
            }
        }

        bacc = warp_sum(bacc); sacc = warp_sum(sacc);
        if (lane == 0) { red[w][0] = bacc; red[w][1] = sacc; }
        __syncthreads();
        if (tid == 0) {
            float b2 = 0.f, s2 = 0.f;
            #pragma unroll
            for (int i = 0; i < 16; i++) { b2 += red[i][0]; s2 += red[i][1]; }
            g_bpart[bid][0] = b2; g_bpart[bid][1] = s2;
        }
    } else {
        // ---------------- prep + corrections gather ----------------
        const int cbid = bid - NDB;
        const int s   = cbid >> 4;       // scale
        const int blk = cbid & 15;       // batch gathered by this block
        const int b = tid >> 5, t = tid & 31;
        const int Wd[3] = {80, 40, 20};
        const int W = Wd[s], HW = W * W;

        const float* tg = targets + (size_t)(b * TT + t) * 5;
        const float cls = tg[0], tx = tg[1], ty = tg[2], tw = tg[3], th = tg[4];

        int gx = (int)floorf(tx * (float)W); gx = min(max(gx, 0), W - 1);
        int gy = (int)floorf(ty * (float)W); gy = min(max(gy, 0), W - 1);

        float best = -1.f; int ba = 0;
        #pragma unroll
        for (int a = 0; a < 3; a++) {
            const float aw = c_anch[s * 6 + a * 2], ah = c_anch[s * 6 + a * 2 + 1];
            const float inter = fminf(tw, aw) * fminf(th, ah);
            const float iou = inter / (tw * th + aw * ah - inter + 1e-6f);
            if (iou > best) { best = iou; ba = a; }   // first-max wins
        }
        const int valid = (best > 0.3f) ? 1 : 0;
        const int lin = (gy * W + gx) * 3 + ba;

        s_lin[tid] = lin;
        s_val[tid] = valid;
        s_meta[tid] = (gy << 16) | (gx << 8) | (ba << 5) | (int)cls;
        {
            const float aw = c_anch[s * 6 + ba * 2], ah = c_anch[s * 6 + ba * 2 + 1];
            s_tb[tid][0] = tx * (float)W - (float)gx;
            s_tb[tid][1] = ty * (float)W - (float)gy;
            s_tb[tid][2] = logf(tw / aw + 1e-6f);
            s_tb[tid][3] = logf(th / ah + 1e-6f);
        }
        __syncthreads();

        int shadowed = 0;
        for (int t2 = t + 1; t2 < TT; t2++) {
            const int i2 = (b << 5) | t2;
            if (s_lin[i2] == lin && s_val[i2]) shadowed = 1;
        }
        s_ok[tid] = valid && !shadowed;
        __syncthreads();

        const float* p = (s == 0) ? p0 : ((s == 1) ? p1 : p2);

        float bd = 0.f, os = 0.f, ns = 0.f, cs = 0.f, nv = 0.f;
        #pragma unroll
        for (int j = 0; j < 2; j++) {
            const int r = (blk << 5) + (w << 1) + j;
            if (s_ok[r]) {
                nv += (lane == 0) ? 1.f : 0.f;
                const int m = s_meta[r];
                const int rgy = m >> 16, rgx = (m >> 8) & 0xff;
                const int rba = (m >> 5) & 3, rcls = m & 31;
                if (lane < 25) {
                    const float x = p[(size_t)(blk * 75 + rba * 25 + lane) * HW
                                      + rgy * W + rgx];
                    if (lane < 4) {
                        const float tb = s_tb[r][lane];
                        bd += tb * tb - 2.f * x * tb;
                    } else if (lane == 4) {
                        os += sp(-x);
                        ns += sp(x);
                    } else {
                        float c = sp(x);
                        if (lane - 5 == rcls) c -= x;
                        cs += c;
                    }
                }
            }
        }
        bd = warp_sum(bd); os = warp_sum(os); ns = warp_sum(ns);
        cs = warp_sum(cs); nv = warp_sum(nv);

        if (lane == 0) {
            red[w][0] = bd; red[w][1] = os; red[w][2] = ns;
            red[w][3] = cs; red[w][4] = nv;
        }
        __syncthreads();
        if (tid == 0) {
            float a0 = 0, a1 = 0, a2 = 0, a3 = 0, a4 = 0;
            #pragma unroll
            for (int i = 0; i < 16; i++) {
                a0 += red[i][0]; a1 += red[i][1]; a2 += red[i][2];
                a3 += red[i][3]; a4 += red[i][4];
            }
            g_cpart[cbid][0] = a0; g_cpart[cbid][1] = a1;
            g_cpart[cbid][2] = a2; g_cpart[cbid][3] = a3;
            g_cpart[cbid][4] = a4;
        }
    }

    // ---------------- last-block final reduction ----------------
    __threadfence();
    __shared__ int is_last;
    __syncthreads();
    if (tid == 0) is_last = (atomicAdd(&g_ticket, 1) == (int)gridDim.x - 1);
    __syncthreads();
    if (!is_last) return;

    float vb[3] = {0, 0, 0}, vs[3] = {0, 0, 0};
    for (int i = tid; i < NDB; i += 512) {
        const int sc = (i >= DB0 + DB1) ? 2 : ((i >= DB0) ? 1 : 0);
        vb[sc] += g_bpart[i][0];
        vs[sc] += g_bpart[i][1];
    }
    float vc[3][5] = {};
    for (int i = tid; i < NCB; i += 512) {
        const int sc = i >> 4;
        #pragma unroll
        for (int q = 0; q < 5; q++) vc[sc][q] += g_cpart[i][q];
    }

    float vals[21];
    #pragma unroll
    for (int sc = 0; sc < 3; sc++) {
        vals[sc * 7 + 0] = vb[sc];
        vals[sc * 7 + 1] = vs[sc];
        #pragma unroll
        for (int q = 0; q < 5; q++) vals[sc * 7 + 2 + q] = vc[sc][q];
    }
    __shared__ float fred[16][21];
    #pragma unroll
    for (int q = 0; q < 21; q++) {
        const float r = warp_sum(vals[q]);
        if (lane == 0) fred[w][q] = r;
    }
    __syncthreads();
    if (tid == 0) {
        float tot[21];
        #pragma unroll
        for (int q = 0; q < 21; q++) {
            float a = 0.f;
            #pragma unroll
            for (int i = 0; i < 16; i++) a += fred[i][q];
            tot[q] = a;
        }
        const int Wd[3] = {80, 40, 20};
        float total = 0.f;
        #pragma unroll
        for (int sc = 0; sc < 3; sc++) {
            const float bb   = tot[sc * 7 + 0];
            const float ss   = tot[sc * 7 + 1];
            const float bdq  = tot[sc * 7 + 2];
            const float osum = tot[sc * 7 + 3];
            const float nsub = tot[sc * 7 + 4];
            const float csum = tot[sc * 7 + 5];
            const float nobj = tot[sc * 7 + 6];
            const float cells = (float)(BB * Wd[sc] * Wd[sc] * 3);
            const float n_obj = nobj + 1e-6f;
            const float n_noobj = (cells - nobj) + 1e-6f;
            const float box_loss   = (bb + bdq) / n_obj;
            const float obj_loss   = osum / n_obj;
            const float noobj_loss = (ss - nsub) / n_noobj;
            const float cls_loss   = csum / n_obj;
            total += 0.05f * box_loss + 1.5f * (obj_loss + 0.5f * noobj_loss)
                   + 0.15f * cls_loss;
        }
        out[0] = total;
        g_ticket = 0;   // reset for next graph replay
    }
}

extern "C" void kernel_launch(void* const* d_in, const int* in_sizes, int n_in,
                              void* d_out, int out_size) {
    const float* p0 = (const float*)d_in[0];
    const float* p1 = (const float*)d_in[1];
    const float* p2 = (const float*)d_in[2];
    const float* tg = (const float*)d_in[3];
    float* out = (float*)d_out;

    fused_kernel<<<NBLK, 512>>>(p0, p1, p2, tg, out);
}

// round 4
// speedup vs baseline: 1.1654x; 1.1654x over previous
#include <cuda_runtime.h>
#include <math.h>

#define BB 16
#define TT 32

__constant__ float c_anch[18] = {
    10.f/8.f, 13.f/8.f, 16.f/8.f, 30.f/8.f, 33.f/8.f, 23.f/8.f,
    30.f/16.f, 61.f/16.f, 62.f/16.f, 45.f/16.f, 59.f/16.f, 119.f/16.f,
    116.f/32.f, 90.f/32.f, 156.f/32.f, 198.f/32.f, 373.f/32.f, 326.f/32.f
};

// Dense geometry (runs of 5 contiguous channels per (b,anchor), run=b*3+a):
//   scale0: 48 runs x 8000 f4 -> 2 blocks/run  -> 96 blocks (4000 f4 each)
//   scale1: 48 runs x 2000 f4 -> 2 runs/block  -> 24 blocks (4000 f4 each)
//   scale2: 48 runs x  500 f4 -> 8 runs/block  ->  6 blocks (4000 f4 each)
// All blocks 512 threads, 8 front-batched float4 loads per thread.
#define DB0 96
#define DB1 24
#define DB2 6
#define NDB (DB0 + DB1 + DB2)    // 126
#define NCB 48                   // corr blocks (16 per scale)
#define NBLK (NDB + NCB)         // 174 total -> single co-resident wave

__device__ float g_bpart[NDB][2];   // per dense block: sum p^2, sum softplus
__device__ float g_cpart[NCB][5];   // per corr block: bd, os, ns, cs, n_valid
__device__ int   g_ticket;          // zero-init; last block resets to 0

__device__ __forceinline__ float sp(float x) {
    // softplus = max(x,0) + log1p(exp(-|x|)); fast 2-MUFU form
    const float z = exp2f(-1.44269504f * fabsf(x));
    return fmaxf(x, 0.f) + 0.69314718f * __log2f(1.f + z);
}

__device__ __forceinline__ float warp_sum(float v) {
    #pragma unroll
    for (int o = 16; o; o >>= 1) v += __shfl_down_sync(0xffffffffu, v, o);
    return v;
}

__global__ void __launch_bounds__(512, 2)
fused_kernel(const float* __restrict__ p0,
             const float* __restrict__ p1,
             const float* __restrict__ p2,
             const float* __restrict__ targets,
             float* __restrict__ out) {
    const int bid = blockIdx.x, tid = threadIdx.x;
    const int lane = tid & 31, w = tid >> 5;

    __shared__ int   s_lin[512];
    __shared__ int   s_val[512];
    __shared__ int   s_ok[512];
    __shared__ int   s_meta[512];
    __shared__ float s_tb[512][4];
    __shared__ float red[16][5];

    if (bid < NDB) {
        // ---------------- dense base pass: 8 independent LDG.128 ----------------
        float4 v[8];
        bool isbox[8];
        const float4 z4 = make_float4(0.f, 0.f, 0.f, 0.f);

        if (bid < DB0) {
            // scale0: run = bid>>1, half h = bid&1; f4 range [h*4000, +4000)
            const int run = bid >> 1, h = bid & 1;
            const float4* b4 = reinterpret_cast<const float4*>(p0)
                             + run * 40000 + h * 4000;
            #pragma unroll
            for (int k = 0; k < 8; k++) {
                const int i = k * 512 + tid;
                const bool ok = i < 4000;
                v[k] = ok ? b4[i] : z4;
                isbox[k] = (!ok) || (h == 0) || (i < 2400);  // f<6400 -> box
            }
        } else if (bid < DB0 + DB1) {
            // scale1: 2 runs per block; run stride 10000 f4, length 2000
            const int j = bid - DB0;
            const float4* b4 = reinterpret_cast<const float4*>(p1) + j * 20000;
            #pragma unroll
            for (int k = 0; k < 8; k++) {
                const int i = k * 512 + tid;
                const bool ok = i < 4000;
                const int r = (i >= 2000) ? 1 : 0;
                const int off = i - 2000 * r;
                v[k] = ok ? b4[r * 10000 + off] : z4;
                isbox[k] = (!ok) || (off < 1600);
            }
        } else {
            // scale2: 8 runs per block; run stride 2500 f4, length 500
            const int j = bid - DB0 - DB1;
            const float4* b4 = reinterpret_cast<const float4*>(p2) + j * 20000;
            #pragma unroll
            for (int k = 0; k < 8; k++) {
                const int i = k * 512 + tid;
                const bool ok = i < 4000;
                const int r = i / 500;           // constant divisor
                const int off = i - 500 * r;
                v[k] = ok ? b4[r * 2500 + off] : z4;
                isbox[k] = (!ok) || (off < 400);
            }
        }

        float bacc = 0.f, sacc = 0.f;
        #pragma unroll
        for (int k = 0; k < 8; k++) {
            if (isbox[k]) {
                bacc += v[k].x * v[k].x + v[k].y * v[k].y
                      + v[k].z * v[k].z + v[k].w * v[k].w;
            } else {
                sacc += sp(v[k].x) + sp(v[k].y) + sp(v[k].z) + sp(v[k].w);
            }
        }

        bacc = warp_sum(bacc); sacc = warp_sum(sacc);
        if (lane == 0) { red[w][0] = bacc; red[w][1] = sacc; }
        __syncthreads();
        if (tid == 0) {
            float b2 = 0.f, s2 = 0.f;
            #pragma unroll
            for (int i = 0; i < 16; i++) { b2 += red[i][0]; s2 += red[i][1]; }
            g_bpart[bid][0] = b2; g_bpart[bid][1] = s2;
        }
    } else {
        // ---------------- prep + corrections gather ----------------
        const int cbid = bid - NDB;
        const int s   = cbid >> 4;       // scale
        const int blk = cbid & 15;       // batch gathered by this block
        const int b = tid >> 5, t = tid & 31;
        const int Wd[3] = {80, 40, 20};
        const int W = Wd[s], HW = W * W;

        const float* tg = targets + (size_t)(b * TT + t) * 5;
        const float cls = tg[0], tx = tg[1], ty = tg[2], tw = tg[3], th = tg[4];

        int gx = (int)floorf(tx * (float)W); gx = min(max(gx, 0), W - 1);
        int gy = (int)floorf(ty * (float)W); gy = min(max(gy, 0), W - 1);

        float best = -1.f; int ba = 0;
        #pragma unroll
        for (int a = 0; a < 3; a++) {
            const float aw = c_anch[s * 6 + a * 2], ah = c_anch[s * 6 + a * 2 + 1];
            const float inter = fminf(tw, aw) * fminf(th, ah);
            const float iou = inter / (tw * th + aw * ah - inter + 1e-6f);
            if (iou > best) { best = iou; ba = a; }   // first-max wins
        }
        const int valid = (best > 0.3f) ? 1 : 0;
        const int lin = (gy * W + gx) * 3 + ba;

        s_lin[tid] = lin;
        s_val[tid] = valid;
        s_meta[tid] = (gy << 16) | (gx << 8) | (ba << 5) | (int)cls;
        {
            const float aw = c_anch[s * 6 + ba * 2], ah = c_anch[s * 6 + ba * 2 + 1];
            s_tb[tid][0] = tx * (float)W - (float)gx;
            s_tb[tid][1] = ty * (float)W - (float)gy;
            s_tb[tid][2] = logf(tw / aw + 1e-6f);
            s_tb[tid][3] = logf(th / ah + 1e-6f);
        }
        __syncthreads();

        int shadowed = 0;
        for (int t2 = t + 1; t2 < TT; t2++) {
            const int i2 = (b << 5) | t2;
            if (s_lin[i2] == lin && s_val[i2]) shadowed = 1;
        }
        s_ok[tid] = valid && !shadowed;
        __syncthreads();

        const float* p = (s == 0) ? p0 : ((s == 1) ? p1 : p2);

        float bd = 0.f, os = 0.f, ns = 0.f, cs = 0.f, nv = 0.f;
        #pragma unroll
        for (int j = 0; j < 2; j++) {
            const int r = (blk << 5) + (w << 1) + j;
            if (s_ok[r]) {
                nv += (lane == 0) ? 1.f : 0.f;
                const int m = s_meta[r];
                const int rgy = m >> 16, rgx = (m >> 8) & 0xff;
                const int rba = (m >> 5) & 3, rcls = m & 31;
                if (lane < 25) {
                    const float x = p[(size_t)(blk * 75 + rba * 25 + lane) * HW
                                      + rgy * W + rgx];
                    if (lane < 4) {
                        const float tb = s_tb[r][lane];
                        bd += tb * tb - 2.f * x * tb;
                    } else if (lane == 4) {
                        os += sp(-x);
                        ns += sp(x);
                    } else {
                        float c = sp(x);
                        if (lane - 5 == rcls) c -= x;
                        cs += c;
                    }
                }
            }
        }
        bd = warp_sum(bd); os = warp_sum(os); ns = warp_sum(ns);
        cs = warp_sum(cs); nv = warp_sum(nv);

        if (lane == 0) {
            red[w][0] = bd; red[w][1] = os; red[w][2] = ns;
            red[w][3] = cs; red[w][4] = nv;
        }
        __syncthreads();
        if (tid == 0) {
            float a0 = 0, a1 = 0, a2 = 0, a3 = 0, a4 = 0;
            #pragma unroll
            for (int i = 0; i < 16; i++) {
                a0 += red[i][0]; a1 += red[i][1]; a2 += red[i][2];
                a3 += red[i][3]; a4 += red[i][4];
            }
            g_cpart[cbid][0] = a0; g_cpart[cbid][1] = a1;
            g_cpart[cbid][2] = a2; g_cpart[cbid][3] = a3;
            g_cpart[cbid][4] = a4;
        }
    }

    // ---------------- last-block final reduction ----------------
    __threadfence();
    __shared__ int is_last;
    __syncthreads();
    if (tid == 0) is_last = (atomicAdd(&g_ticket, 1) == (int)gridDim.x - 1);
    __syncthreads();
    if (!is_last) return;

    float vb[3] = {0, 0, 0}, vs[3] = {0, 0, 0};
    for (int i = tid; i < NDB; i += 512) {
        const int sc = (i >= DB0 + DB1) ? 2 : ((i >= DB0) ? 1 : 0);
        vb[sc] += g_bpart[i][0];
        vs[sc] += g_bpart[i][1];
    }
    float vc[3][5] = {};
    for (int i = tid; i < NCB; i += 512) {
        const int sc = i >> 4;
        #pragma unroll
        for (int q = 0; q < 5; q++) vc[sc][q] += g_cpart[i][q];
    }

    float vals[21];
    #pragma unroll
    for (int sc = 0; sc < 3; sc++) {
        vals[sc * 7 + 0] = vb[sc];
        vals[sc * 7 + 1] = vs[sc];
        #pragma unroll
        for (int q = 0; q < 5; q++) vals[sc * 7 + 2 + q] = vc[sc][q];
    }
    __shared__ float fred[16][21];
    #pragma unroll
    for (int q = 0; q < 21; q++) {
        const float r = warp_sum(vals[q]);
        if (lane == 0) fred[w][q] = r;
    }
    __syncthreads();
    if (tid == 0) {
        float tot[21];
        #pragma unroll
        for (int q = 0; q < 21; q++) {
            float a = 0.f;
            #pragma unroll
            for (int i = 0; i < 16; i++) a += fred[i][q];
            tot[q] = a;
        }
        const int Wd[3] = {80, 40, 20};
        float total = 0.f;
        #pragma unroll
        for (int sc = 0; sc < 3; sc++) {
            const float bb   = tot[sc * 7 + 0];
            const float ss   = tot[sc * 7 + 1];
            const float bdq  = tot[sc * 7 + 2];
            const float osum = tot[sc * 7 + 3];
            const float nsub = tot[sc * 7 + 4];
            const float csum = tot[sc * 7 + 5];
            const float nobj = tot[sc * 7 + 6];
            const float cells = (float)(BB * Wd[sc] * Wd[sc] * 3);
            const float n_obj = nobj + 1e-6f;
            const float n_noobj = (cells - nobj) + 1e-6f;
            const float box_loss   = (bb + bdq) / n_obj;
            const float obj_loss   = osum / n_obj;
            const float noobj_loss = (ss - nsub) / n_noobj;
            const float cls_loss   = csum / n_obj;
            total += 0.05f * box_loss + 1.5f * (obj_loss + 0.5f * noobj_loss)
                   + 0.15f * cls_loss;
        }
        out[0] = total;
        g_ticket = 0;   // reset for next graph replay
    }
}

extern "C" void kernel_launch(void* const* d_in, const int* in_sizes, int n_in,
                              void* d_out, int out_size) {
    const float* p0 = (const float*)d_in[0];
    const float* p1 = (const float*)d_in[1];
    const float* p2 = (const float*)d_in[2];
    const float* tg = (const float*)d_in[3];
    float* out = (float*)d_out;

    fused_kernel<<<NBLK, 512>>>(p0, p1, p2, tg, out);
}